// round 13
// baseline (speedup 1.0000x reference)
#include <cuda_runtime.h>
#include <cuda_fp16.h>
#include <cstdint>
#include <math.h>

#define N_  8
#define C_  512
#define T_  4096
#define TPAD (T_+2)
#define G_  32
#define EPS_ 1e-5f
#define OFFSET_ELEMS (N_*2*T_)

#define TMT 128
#define TNT 128
#define NCHUNK 24   // 3 taps * (512/64)
#define STAGES 3
#define STAGE_BYTES 32768   // A 16K | B 16K
#define NTB (T_/TNT)        // 32 t-blocks

// ---------------- device scratch ----------------
__device__ __half g_h16[(size_t)N_*C_*T_];       // conv1 raw output fp16 [n][c][t]
__device__ float g_mean[N_*G_], g_rstd[N_*G_];
__device__ float g_psum[N_][G_][NTB], g_psumsq[N_][G_][NTB];
// weights: [conv][tap][o][ci] fp16
__device__ __half g_W[2][3*C_*C_];
// T-major activation planes, padded rows [n][TPAD][C] (rows 0 and TPAD-1 are guards)
__device__ __half g_xT[(size_t)N_*TPAD*C_];
__device__ __half g_hT[(size_t)N_*TPAD*C_];
__device__ __half g_S0[(size_t)N_*TPAD*C_];
__device__ __half g_S2[(size_t)N_*TPAD*C_];

// ---------------- PTX helpers ----------------
__device__ __forceinline__ uint32_t smem_u32(const void* p) {
    uint32_t a;
    asm("{ .reg .u64 t; cvta.to.shared.u64 t, %1; cvt.u32.u64 %0, t; }" : "=r"(a) : "l"(p));
    return a;
}
__device__ __forceinline__ void cp_async16(uint32_t saddr, const void* gaddr) {
    asm volatile("cp.async.cg.shared.global [%0], [%1], 16;" :: "r"(saddr), "l"(gaddr));
}
__device__ __forceinline__ void ldsm4(uint32_t* r, uint32_t addr) {
    asm volatile("ldmatrix.sync.aligned.m8n8.x4.shared.b16 {%0,%1,%2,%3}, [%4];"
        : "=r"(r[0]), "=r"(r[1]), "=r"(r[2]), "=r"(r[3]) : "r"(addr));
}
__device__ __forceinline__ void mma_f32(float* d, const uint32_t* a, uint32_t b0, uint32_t b1) {
    asm volatile("mma.sync.aligned.m16n8k16.row.col.f32.f16.f16.f32 "
        "{%0,%1,%2,%3}, {%4,%5,%6,%7}, {%8,%9}, {%0,%1,%2,%3};"
        : "+f"(d[0]), "+f"(d[1]), "+f"(d[2]), "+f"(d[3])
        : "r"(a[0]), "r"(a[1]), "r"(a[2]), "r"(a[3]), "r"(b0), "r"(b1));
}

// ---------------- prep: weights -> fp16, [tap][o][ci] ----------------
__global__ __launch_bounds__(256) void prep_w_kernel(const float* __restrict__ w1,
                                                     const float* __restrict__ w2) {
    const int conv = blockIdx.y;
    const float* w = conv ? w2 : w1;
    __half* W = g_W[conv];
    const int total = 3 * C_ * C_;
    for (int idx = blockIdx.x * 256 + threadIdx.x; idx < total; idx += gridDim.x * 256) {
        int k = idx / (C_ * C_);
        int rem = idx % (C_ * C_);
        int o = rem / C_, ci = rem % C_;
        W[idx] = __float2half_rn(w[((size_t)o * C_ + ci) * 3 + k]);
    }
}

// ---------------- prep: feat [n][c][t] -> xT fp16 [n][1+t][c] (vectorized) ----------------
// also zeroes guard rows when t0 == 0
__global__ __launch_bounds__(256) void prep_x_kernel(const float* __restrict__ feat) {
    __shared__ float sx[64][65];
    int n = blockIdx.z, c0 = blockIdx.y * 64, t0 = blockIdx.x * 64;
    const float* xb = feat + ((size_t)n * C_ + c0) * T_ + t0;
    // load: float2 along t
    for (int i = threadIdx.x; i < 64 * 32; i += 256) {
        int ci = i >> 5, tj = (i & 31) * 2;
        float2 v = *reinterpret_cast<const float2*>(xb + (size_t)ci * T_ + tj);
        sx[ci][tj] = v.x; sx[ci][tj + 1] = v.y;
    }
    __syncthreads();
    // store: half2 along c
    for (int i = threadIdx.x; i < 32 * 64; i += 256) {
        int t = i >> 5, ci2 = (i & 31) * 2;
        size_t dst = ((size_t)n * TPAD + 1 + t0 + t) * C_ + c0 + ci2;
        *reinterpret_cast<__half2*>(g_xT + dst) =
            __floats2half2_rn(sx[ci2][t], sx[ci2 + 1][t]);
    }
    // guard rows
    if (blockIdx.x == 0 && threadIdx.x < 64) {
        int ci = threadIdx.x;
        __half z = __float2half_rn(0.f);
        g_xT[((size_t)n * TPAD) * C_ + c0 + ci] = z;
        g_xT[((size_t)n * TPAD + TPAD - 1) * C_ + c0 + ci] = z;
    }
}

// ---------------- fp16 MMA GEMM (128x128 tile, warp 32x64, 3 stages) ----------------
extern __shared__ char smem_raw[];
__global__ __launch_bounds__(256) void gemm_kernel(
    const __half* __restrict__ W,
    const __half* __restrict__ B0, const __half* __restrict__ B1, const __half* __restrict__ B2,
    int r0off, int r1off, int r2off,
    const float* __restrict__ bias, float* __restrict__ out32, __half* __restrict__ out16,
    int relu, int stats)
{
    const int tid = threadIdx.x, lane = tid & 31, wid = tid >> 5;
    const int nB = blockIdx.z, o0 = blockIdx.y * TMT, t0 = blockIdx.x * TNT;

    const uint32_t sb = smem_u32(smem_raw);

    // warp tile: 32 rows (m) x 64 cols (n); 4 m-warps x 2 n-warps
    const int m0 = (wid >> 1) * 32;
    const int nw = (wid & 1) * 64;
    const int arow = lane & 15, acb = lane >> 4;
    const int brow = (lane & 7) + ((lane >> 4) << 3), bcb = (lane >> 3) & 1;
    uint32_t aoff[2], a7[2], boff[4], b7[4];
    #pragma unroll
    for (int mf = 0; mf < 2; mf++) {
        int r = m0 + mf * 16 + arow;
        aoff[mf] = (uint32_t)(r * 128); a7[mf] = (uint32_t)(r & 7);
    }
    #pragma unroll
    for (int p = 0; p < 4; p++) {
        int r = nw + p * 16 + brow;
        boff[p] = (uint32_t)(r * 128); b7[p] = (uint32_t)(r & 7);
    }

    float acc[2][8][4];
    #pragma unroll
    for (int a = 0; a < 2; a++)
        #pragma unroll
        for (int b = 0; b < 8; b++)
            #pragma unroll
            for (int c = 0; c < 4; c++) acc[a][b][c] = 0.f;

    auto load_chunk = [&](int c, int s) {
        const int tap = c >> 3, ci0 = (c & 7) * 64;
        const __half* bsrc; int ro;
        if (tap == 0)      { bsrc = B0; ro = r0off; }
        else if (tap == 1) { bsrc = B1; ro = r1off; }
        else               { bsrc = B2; ro = r2off; }
        const size_t brow0 = (size_t)nB * TPAD + 1 + t0 + ro;
        const __half* wsrc = W + ((size_t)tap * C_ + o0) * C_ + ci0;
        const uint32_t st = sb + (uint32_t)s * (uint32_t)STAGE_BYTES;
        // A: 128 rows x 8 chunks of 16B
        #pragma unroll
        for (int it = 0; it < 4; it++) {
            int i = tid + it * 256;          // 0..1023
            int row = i >> 3, q = i & 7;
            uint32_t so = (uint32_t)(row * 128 + ((q ^ (row & 7)) << 4));
            cp_async16(st + so, wsrc + (size_t)row * C_ + q * 8);
        }
        // B: 128 rows x 8 chunks
        #pragma unroll
        for (int it = 0; it < 4; it++) {
            int i = tid + it * 256;          // 0..1023
            int row = i >> 3, q = i & 7;
            uint32_t so = (uint32_t)(row * 128 + ((q ^ (row & 7)) << 4));
            cp_async16(st + 16384u + so, bsrc + (brow0 + row) * C_ + ci0 + q * 8);
        }
        asm volatile("cp.async.commit_group;" ::: "memory");
    };

    auto compute = [&](int s) {
        const uint32_t Ab = sb + (uint32_t)s * (uint32_t)STAGE_BYTES;
        const uint32_t Bb = Ab + 16384u;
        #pragma unroll
        for (int ks = 0; ks < 4; ks++) {
            uint32_t ah[2][4], bhv[4][4];
            #pragma unroll
            for (int mf = 0; mf < 2; mf++) {
                uint32_t off = aoff[mf] + ((((uint32_t)(2*ks) + acb) ^ a7[mf]) << 4);
                ldsm4(ah[mf], Ab + off);
            }
            #pragma unroll
            for (int p = 0; p < 4; p++) {
                uint32_t off = boff[p] + ((((uint32_t)(2*ks) + bcb) ^ b7[p]) << 4);
                ldsm4(bhv[p], Bb + off);
            }
            #pragma unroll
            for (int mf = 0; mf < 2; mf++) {
                #pragma unroll
                for (int nf = 0; nf < 8; nf++) {
                    int p = nf >> 1, j = (nf & 1) * 2;
                    mma_f32(acc[mf][nf], ah[mf], bhv[p][j], bhv[p][j+1]);
                }
            }
        }
    };

    // 3-stage pipeline, single barrier per chunk
    load_chunk(0, 0);
    load_chunk(1, 1);
    for (int c = 0; c < NCHUNK; c++) {
        if (c >= NCHUNK - 2) asm volatile("cp.async.wait_group 0;" ::: "memory");
        else                 asm volatile("cp.async.wait_group 1;" ::: "memory");
        __syncthreads();
        if (c + 2 < NCHUNK) load_chunk(c + 2, (c + 2) % STAGES);
        compute(c % STAGES);
    }

    // epilogue (+ optional fused GroupNorm partial stats, deterministic)
    __shared__ float ws[8][2][2];
    #pragma unroll
    for (int mf = 0; mf < 2; mf++) {
        int rowA = o0 + m0 + mf * 16 + (lane >> 2);
        int rowB = rowA + 8;
        float bA = bias[rowA], bB = bias[rowB];
        float s = 0.f, q = 0.f;
        #pragma unroll
        for (int nf = 0; nf < 8; nf++) {
            int col = nw + nf * 8 + (lane & 3) * 2;
            float2 vA = make_float2(acc[mf][nf][0] + bA, acc[mf][nf][1] + bA);
            float2 vB = make_float2(acc[mf][nf][2] + bB, acc[mf][nf][3] + bB);
            if (stats) {
                s += vA.x + vA.y + vB.x + vB.y;
                q += vA.x*vA.x + vA.y*vA.y + vB.x*vB.x + vB.y*vB.y;
            }
            if (relu) {
                vA.x = fmaxf(vA.x, 0.f); vA.y = fmaxf(vA.y, 0.f);
                vB.x = fmaxf(vB.x, 0.f); vB.y = fmaxf(vB.y, 0.f);
            }
            if (out16) {
                __half* pA = out16 + ((size_t)nB * C_ + rowA) * T_ + t0;
                __half* pB = out16 + ((size_t)nB * C_ + rowB) * T_ + t0;
                *reinterpret_cast<__half2*>(pA + col) = __floats2half2_rn(vA.x, vA.y);
                *reinterpret_cast<__half2*>(pB + col) = __floats2half2_rn(vB.x, vB.y);
            } else {
                float* pA = out32 + ((size_t)nB * C_ + rowA) * T_ + t0;
                float* pB = out32 + ((size_t)nB * C_ + rowB) * T_ + t0;
                *reinterpret_cast<float2*>(pA + col) = vA;
                *reinterpret_cast<float2*>(pB + col) = vB;
            }
        }
        if (stats) {
            #pragma unroll
            for (int d = 16; d > 0; d >>= 1) {
                s += __shfl_xor_sync(0xffffffffu, s, d);
                q += __shfl_xor_sync(0xffffffffu, q, d);
            }
            if (lane == 0) { ws[wid][mf][0] = s; ws[wid][mf][1] = q; }
        }
    }
    if (stats) {
        __syncthreads();
        if (tid < 8) {
            int mw = tid >> 1, mf = tid & 1;
            float s = ws[mw*2+0][mf][0] + ws[mw*2+1][mf][0];
            float q = ws[mw*2+0][mf][1] + ws[mw*2+1][mf][1];
            int g = o0 / 16 + tid;
            g_psum[nB][g][blockIdx.x]   = s;
            g_psumsq[nB][g][blockIdx.x] = q;
        }
    }
}

// ---------------- finalize GroupNorm stats ----------------
__global__ void gn_finalize_kernel() {
    int idx = blockIdx.x * blockDim.x + threadIdx.x;
    if (idx >= N_ * G_) return;
    int n = idx / G_, g = idx % G_;
    float s = 0.f, q = 0.f;
    #pragma unroll
    for (int b = 0; b < NTB; b++) { s += g_psum[n][g][b]; q += g_psumsq[n][g][b]; }
    const float M = 16.f * T_;
    float m = s / M;
    float var = q / M - m * m;
    g_mean[idx] = m;
    g_rstd[idx] = rsqrtf(var + EPS_);
}

// ---------------- normalize+relu -> hT fp16 (transposed), vectorized ----------------
__global__ __launch_bounds__(256) void norm_t_kernel(const float* __restrict__ gamma,
                                                     const float* __restrict__ beta) {
    __shared__ float st[64][65];
    int n = blockIdx.z, c0 = blockIdx.y * 64, t0 = blockIdx.x * 64;
    for (int i = threadIdx.x; i < 64 * 32; i += 256) {
        int ci = i >> 5, tj = (i & 31) * 2;
        int c = c0 + ci;
        __half2 hv = *reinterpret_cast<const __half2*>(
            g_h16 + ((size_t)n * C_ + c) * T_ + t0 + tj);
        int gi = n * G_ + (c >> 4);
        float mu = g_mean[gi], rs = g_rstd[gi], ga = gamma[c], be = beta[c];
        float v0 = fmaxf((__half2float(hv.x) - mu) * rs * ga + be, 0.f);
        float v1 = fmaxf((__half2float(hv.y) - mu) * rs * ga + be, 0.f);
        st[ci][tj] = v0; st[ci][tj + 1] = v1;
    }
    __syncthreads();
    for (int i = threadIdx.x; i < 32 * 64; i += 256) {
        int t = i >> 5, ci2 = (i & 31) * 2;
        size_t dst = ((size_t)n * TPAD + 1 + t0 + t) * C_ + c0 + ci2;
        *reinterpret_cast<__half2*>(g_hT + dst) =
            __floats2half2_rn(st[ci2][t], st[ci2 + 1][t]);
    }
}

// ---------------- bilinear sampling -> S0/S2 fp16 (reads hT, vectorized) ----------------
__global__ __launch_bounds__(256) void sample_kernel(const float* __restrict__ locs,
                                                     const int* __restrict__ stride_p) {
    const int n = blockIdx.y;
    int sv = *stride_p;
    float fs = (sv > 0 && sv < 1000000) ? (float)sv : __int_as_float(sv);

    const int ci2 = threadIdx.x;   // half2 index: channels 2*ci2, 2*ci2+1

    #pragma unroll
    for (int tt = 0; tt < 4; tt++) {
        int t = blockIdx.x * 4 + tt;
        float y1 = locs[((size_t)n * 2 + 0) * T_ + t] / fs;
        float y2 = locs[((size_t)n * 2 + 1) * T_ + t] / fs;

        float pos0 = (float)t - 1.0f - y1;
        float f0 = floorf(pos0);
        float wb0 = pos0 - f0;
        int i00 = (int)f0, i01 = i00 + 1;
        float m00 = (i00 >= 0 && i00 < T_) ? 1.f : 0.f;
        float m01 = (i01 >= 0 && i01 < T_) ? 1.f : 0.f;
        size_t r00 = ((size_t)n * TPAD + 1 + min(max(i00, 0), T_ - 1)) * C_;
        size_t r01 = ((size_t)n * TPAD + 1 + min(max(i01, 0), T_ - 1)) * C_;

        float pos2 = (float)t + 1.0f + y2;
        float f2 = floorf(pos2);
        float wb2 = pos2 - f2;
        int i20 = (int)f2, i21 = i20 + 1;
        float m20 = (i20 >= 0 && i20 < T_) ? 1.f : 0.f;
        float m21 = (i21 >= 0 && i21 < T_) ? 1.f : 0.f;
        size_t r20 = ((size_t)n * TPAD + 1 + min(max(i20, 0), T_ - 1)) * C_;
        size_t r21 = ((size_t)n * TPAD + 1 + min(max(i21, 0), T_ - 1)) * C_;

        size_t dst = ((size_t)n * TPAD + 1 + t) * C_;

        __half2 a0 = ((const __half2*)(g_hT + r00))[ci2];
        __half2 b0 = ((const __half2*)(g_hT + r01))[ci2];
        __half2 a2 = ((const __half2*)(g_hT + r20))[ci2];
        __half2 b2 = ((const __half2*)(g_hT + r21))[ci2];

        float w0a = (1.f - wb0) * m00, w0b = wb0 * m01;
        float w2a = (1.f - wb2) * m20, w2b = wb2 * m21;

        float s0x = __half2float(a0.x) * w0a + __half2float(b0.x) * w0b;
        float s0y = __half2float(a0.y) * w0a + __half2float(b0.y) * w0b;
        float s2x = __half2float(a2.x) * w2a + __half2float(b2.x) * w2b;
        float s2y = __half2float(a2.y) * w2a + __half2float(b2.y) * w2b;

        ((__half2*)(g_S0 + dst))[ci2] = __floats2half2_rn(s0x, s0y);
        ((__half2*)(g_S2 + dst))[ci2] = __floats2half2_rn(s2x, s2y);
    }
}

// ---------------- final 512->2 conv (parallel over t and channel groups) ----------------
__global__ __launch_bounds__(256) void outconv_kernel(const float* __restrict__ W,
                                                      const float* __restrict__ b,
                                                      const float* __restrict__ feat,
                                                      float* __restrict__ out) {
    __shared__ float sW[2 * C_ * 3];
    __shared__ float red[4][64][2];
    for (int l = threadIdx.x; l < 2 * C_ * 3; l += 256) sW[l] = W[l];
    __syncthreads();

    const int tl = threadIdx.x & 63;
    const int cg = threadIdx.x >> 6;           // 0..3
    const int t = blockIdx.x * 64 + tl;
    const int n = blockIdx.y;
    const float* fb = feat + (size_t)n * C_ * T_;
    float a0 = 0.f, a1 = 0.f;
    bool lok = (t >= 1), rok = (t < T_ - 1);
    const int c0 = cg * 128;
    for (int i = c0; i < c0 + 128; i++) {
        const float* fr = fb + (size_t)i * T_ + t;
        float vm = lok ? fr[-1] : 0.0f;
        float v0 = fr[0];
        float vp = rok ? fr[1] : 0.0f;
        a0 = fmaf(sW[i*3+0], vm, a0);
        a0 = fmaf(sW[i*3+1], v0, a0);
        a0 = fmaf(sW[i*3+2], vp, a0);
        a1 = fmaf(sW[(C_+i)*3+0], vm, a1);
        a1 = fmaf(sW[(C_+i)*3+1], v0, a1);
        a1 = fmaf(sW[(C_+i)*3+2], vp, a1);
    }
    red[cg][tl][0] = a0;
    red[cg][tl][1] = a1;
    __syncthreads();
    if (cg == 0) {
        float r0 = b[0] + red[0][tl][0] + red[1][tl][0] + red[2][tl][0] + red[3][tl][0];
        float r1 = b[1] + red[0][tl][1] + red[1][tl][1] + red[2][tl][1] + red[3][tl][1];
        out[(size_t)n * 2 * T_ + t]       = r0;
        out[((size_t)n * 2 + 1) * T_ + t] = r1;
    }
}

// ---------------------------------------------------------------------------
extern "C" void kernel_launch(void* const* d_in, const int* in_sizes, int n_in,
                              void* d_out, int out_size) {
    const float* feat   = (const float*)d_in[0];
    const float* locs   = (const float*)d_in[1];
    const float* conv_w = (const float*)d_in[2];
    const float* conv_b = (const float*)d_in[3];
    const float* gn_g   = (const float*)d_in[4];
    const float* gn_b   = (const float*)d_in[5];
    const float* dcn_w  = (const float*)d_in[6];
    const float* dcn_b  = (const float*)d_in[7];
    const float* out_w  = (const float*)d_in[8];
    const float* out_b  = (const float*)d_in[9];
    const int*   stride = (const int*)d_in[10];

    float* out      = (float*)d_out;
    float* out_feat = (float*)d_out + OFFSET_ELEMS;

    __half *w1, *w2, *xt, *ht, *s0, *s2, *hbuf16;
    cudaGetSymbolAddress((void**)&w1, g_W);  w2 = w1 + 3*C_*C_;
    cudaGetSymbolAddress((void**)&xt, g_xT);
    cudaGetSymbolAddress((void**)&ht, g_hT);
    cudaGetSymbolAddress((void**)&s0, g_S0);
    cudaGetSymbolAddress((void**)&s2, g_S2);
    cudaGetSymbolAddress((void**)&hbuf16, g_h16);

    const int SMEM_BYTES = STAGES * STAGE_BYTES;   // 96 KB
    cudaFuncSetAttribute(gemm_kernel, cudaFuncAttributeMaxDynamicSharedMemorySize, SMEM_BYTES);

    dim3 tr_grid(T_/64, C_/64, N_);
    dim3 gemm_grid(T_/TNT, C_/TMT, N_);   // (32, 4, 8) = 1024

    prep_w_kernel<<<dim3(512, 2), 256>>>(conv_w, dcn_w);
    prep_x_kernel<<<tr_grid, 256>>>(feat);
    gemm_kernel<<<gemm_grid, 256, SMEM_BYTES>>>(w1,
        xt, xt, xt, -1, 0, 1, conv_b, nullptr, hbuf16, 0, 1);
    gn_finalize_kernel<<<1, 256>>>();
    norm_t_kernel<<<tr_grid, 256>>>(gn_g, gn_b);
    sample_kernel<<<dim3(T_/4, N_), 256>>>(locs, stride);
    gemm_kernel<<<gemm_grid, 256, SMEM_BYTES>>>(w2,
        s0, ht, s2, 0, 0, 0, dcn_b, out_feat, nullptr, 1, 0);
    outconv_kernel<<<dim3(T_/64, N_), 256>>>(out_w, out_b, out_feat, out);
}

// round 14
// speedup vs baseline: 1.3770x; 1.3770x over previous
#include <cuda_runtime.h>
#include <cuda_fp16.h>
#include <cstdint>
#include <math.h>

#define N_  8
#define C_  512
#define T_  4096
#define TPAD (T_+2)
#define G_  32
#define EPS_ 1e-5f
#define OFFSET_ELEMS (N_*2*T_)

#define TMT 128
#define TNT 128
#define NCHUNK 24   // 3 taps * (512/64)
#define STAGES 3
#define STAGE_BYTES 32768   // A 16K | B 16K
#define NTB (T_/TNT)        // 32 t-blocks

// ---------------- device scratch ----------------
__device__ __half g_h16[(size_t)N_*C_*T_];       // conv1 raw output fp16 [n][c][t]
__device__ float g_mean[N_*G_], g_rstd[N_*G_];
__device__ float g_psum[N_][G_][NTB], g_psumsq[N_][G_][NTB];
// weights: [conv][tap][o][ci] fp16
__device__ __half g_W[2][3*C_*C_];
// T-major activation planes, padded rows [n][TPAD][C] (rows 0 and TPAD-1 are guards)
__device__ __half g_xT[(size_t)N_*TPAD*C_];
__device__ __half g_hT[(size_t)N_*TPAD*C_];
__device__ __half g_S0[(size_t)N_*TPAD*C_];
__device__ __half g_S2[(size_t)N_*TPAD*C_];

// ---------------- PTX helpers ----------------
__device__ __forceinline__ uint32_t smem_u32(const void* p) {
    uint32_t a;
    asm("{ .reg .u64 t; cvta.to.shared.u64 t, %1; cvt.u32.u64 %0, t; }" : "=r"(a) : "l"(p));
    return a;
}
__device__ __forceinline__ void cp_async16(uint32_t saddr, const void* gaddr) {
    asm volatile("cp.async.cg.shared.global [%0], [%1], 16;" :: "r"(saddr), "l"(gaddr));
}
__device__ __forceinline__ void ldsm4(uint32_t* r, uint32_t addr) {
    asm volatile("ldmatrix.sync.aligned.m8n8.x4.shared.b16 {%0,%1,%2,%3}, [%4];"
        : "=r"(r[0]), "=r"(r[1]), "=r"(r[2]), "=r"(r[3]) : "r"(addr));
}
__device__ __forceinline__ void mma_f32(float* d, const uint32_t* a, uint32_t b0, uint32_t b1) {
    asm volatile("mma.sync.aligned.m16n8k16.row.col.f32.f16.f16.f32 "
        "{%0,%1,%2,%3}, {%4,%5,%6,%7}, {%8,%9}, {%0,%1,%2,%3};"
        : "+f"(d[0]), "+f"(d[1]), "+f"(d[2]), "+f"(d[3])
        : "r"(a[0]), "r"(a[1]), "r"(a[2]), "r"(a[3]), "r"(b0), "r"(b1));
}

// ---------------- prep: weights -> fp16, [tap][o][ci] ----------------
__global__ __launch_bounds__(256) void prep_w_kernel(const float* __restrict__ w1,
                                                     const float* __restrict__ w2) {
    const int conv = blockIdx.y;
    const float* w = conv ? w2 : w1;
    __half* W = g_W[conv];
    const int total = 3 * C_ * C_;
    for (int idx = blockIdx.x * 256 + threadIdx.x; idx < total; idx += gridDim.x * 256) {
        int k = idx / (C_ * C_);
        int rem = idx % (C_ * C_);
        int o = rem / C_, ci = rem % C_;
        W[idx] = __float2half_rn(w[((size_t)o * C_ + ci) * 3 + k]);
    }
}

// ---------------- prep: feat [n][c][t] -> xT fp16 [n][1+t][c] ----------------
__global__ __launch_bounds__(256) void prep_x_kernel(const float* __restrict__ feat) {
    __shared__ float sx[64][65];
    int n = blockIdx.z, c0 = blockIdx.y * 64, t0 = blockIdx.x * 64;
    const float* xb = feat + ((size_t)n * C_ + c0) * T_ + t0;
    for (int i = threadIdx.x; i < 64 * 64; i += 256) {
        int ci = i >> 6, t = i & 63;
        sx[ci][t] = xb[(size_t)ci * T_ + t];
    }
    __syncthreads();
    for (int i = threadIdx.x; i < 64 * 64; i += 256) {
        int ci = i & 63, t = i >> 6;
        size_t dst = ((size_t)n * TPAD + 1 + t0 + t) * C_ + c0 + ci;
        g_xT[dst] = __float2half_rn(sx[ci][t]);
    }
}

__global__ __launch_bounds__(256) void zero_guard_kernel() {
    int idx = blockIdx.x * 256 + threadIdx.x;      // over N_*C_
    if (idx >= N_ * C_) return;
    int n = idx / C_, ci = idx % C_;
    size_t r0 = ((size_t)n * TPAD) * C_ + ci;
    size_t r1 = ((size_t)n * TPAD + TPAD - 1) * C_ + ci;
    __half z = __float2half_rn(0.f);
    g_xT[r0] = z; g_xT[r1] = z;
}

// ---------------- fp16 MMA GEMM (128x128 tile, warp 32x64, 3 stages) ----------------
extern __shared__ char smem_raw[];
__global__ __launch_bounds__(256) void gemm_kernel(
    const __half* __restrict__ W,
    const __half* __restrict__ B0, const __half* __restrict__ B1, const __half* __restrict__ B2,
    int r0off, int r1off, int r2off,
    const float* __restrict__ bias, float* __restrict__ out32, __half* __restrict__ out16,
    int relu, int stats)
{
    const int tid = threadIdx.x, lane = tid & 31, wid = tid >> 5;
    const int nB = blockIdx.z, o0 = blockIdx.y * TMT, t0 = blockIdx.x * TNT;

    const uint32_t sb = smem_u32(smem_raw);

    // warp tile: 32 rows (m) x 64 cols (n); 4 m-warps x 2 n-warps
    const int m0 = (wid >> 1) * 32;
    const int nw = (wid & 1) * 64;
    const int arow = lane & 15, acb = lane >> 4;
    const int brow = (lane & 7) + ((lane >> 4) << 3), bcb = (lane >> 3) & 1;
    uint32_t aoff[2], a7[2], boff[4], b7[4];
    #pragma unroll
    for (int mf = 0; mf < 2; mf++) {
        int r = m0 + mf * 16 + arow;
        aoff[mf] = (uint32_t)(r * 128); a7[mf] = (uint32_t)(r & 7);
    }
    #pragma unroll
    for (int p = 0; p < 4; p++) {
        int r = nw + p * 16 + brow;
        boff[p] = (uint32_t)(r * 128); b7[p] = (uint32_t)(r & 7);
    }

    float acc[2][8][4];
    #pragma unroll
    for (int a = 0; a < 2; a++)
        #pragma unroll
        for (int b = 0; b < 8; b++)
            #pragma unroll
            for (int c = 0; c < 4; c++) acc[a][b][c] = 0.f;

    auto load_chunk = [&](int c, int s) {
        const int tap = c >> 3, ci0 = (c & 7) * 64;
        const __half* bsrc; int ro;
        if (tap == 0)      { bsrc = B0; ro = r0off; }
        else if (tap == 1) { bsrc = B1; ro = r1off; }
        else               { bsrc = B2; ro = r2off; }
        const size_t brow0 = (size_t)nB * TPAD + 1 + t0 + ro;
        const __half* wsrc = W + ((size_t)tap * C_ + o0) * C_ + ci0;
        const uint32_t st = sb + (uint32_t)s * (uint32_t)STAGE_BYTES;
        // A: 128 rows x 8 chunks of 16B
        #pragma unroll
        for (int it = 0; it < 4; it++) {
            int i = tid + it * 256;          // 0..1023
            int row = i >> 3, q = i & 7;
            uint32_t so = (uint32_t)(row * 128 + ((q ^ (row & 7)) << 4));
            cp_async16(st + so, wsrc + (size_t)row * C_ + q * 8);
        }
        // B: 128 rows x 8 chunks
        #pragma unroll
        for (int it = 0; it < 4; it++) {
            int i = tid + it * 256;          // 0..1023
            int row = i >> 3, q = i & 7;
            uint32_t so = (uint32_t)(row * 128 + ((q ^ (row & 7)) << 4));
            cp_async16(st + 16384u + so, bsrc + (brow0 + row) * C_ + ci0 + q * 8);
        }
        asm volatile("cp.async.commit_group;" ::: "memory");
    };

    auto compute = [&](int s) {
        const uint32_t Ab = sb + (uint32_t)s * (uint32_t)STAGE_BYTES;
        const uint32_t Bb = Ab + 16384u;
        #pragma unroll
        for (int ks = 0; ks < 4; ks++) {
            uint32_t ah[2][4], bhv[4][4];
            #pragma unroll
            for (int mf = 0; mf < 2; mf++) {
                uint32_t off = aoff[mf] + ((((uint32_t)(2*ks) + acb) ^ a7[mf]) << 4);
                ldsm4(ah[mf], Ab + off);
            }
            #pragma unroll
            for (int p = 0; p < 4; p++) {
                uint32_t off = boff[p] + ((((uint32_t)(2*ks) + bcb) ^ b7[p]) << 4);
                ldsm4(bhv[p], Bb + off);
            }
            #pragma unroll
            for (int mf = 0; mf < 2; mf++) {
                #pragma unroll
                for (int nf = 0; nf < 8; nf++) {
                    int p = nf >> 1, j = (nf & 1) * 2;
                    mma_f32(acc[mf][nf], ah[mf], bhv[p][j], bhv[p][j+1]);
                }
            }
        }
    };

    // 3-stage pipeline, single barrier per chunk:
    // iter c: wait(chunk c) -> sync -> prefetch(c+2 into stage (c+2)%3) -> compute(c)
    load_chunk(0, 0);
    load_chunk(1, 1);
    for (int c = 0; c < NCHUNK; c++) {
        if (c >= NCHUNK - 2) asm volatile("cp.async.wait_group 0;" ::: "memory");
        else                 asm volatile("cp.async.wait_group 1;" ::: "memory");
        __syncthreads();
        if (c + 2 < NCHUNK) load_chunk(c + 2, (c + 2) % STAGES);
        compute(c % STAGES);
    }

    // epilogue (+ optional fused GroupNorm partial stats, deterministic)
    __shared__ float ws[8][2][2];
    #pragma unroll
    for (int mf = 0; mf < 2; mf++) {
        int rowA = o0 + m0 + mf * 16 + (lane >> 2);
        int rowB = rowA + 8;
        float bA = bias[rowA], bB = bias[rowB];
        float s = 0.f, q = 0.f;
        #pragma unroll
        for (int nf = 0; nf < 8; nf++) {
            int col = nw + nf * 8 + (lane & 3) * 2;
            float2 vA = make_float2(acc[mf][nf][0] + bA, acc[mf][nf][1] + bA);
            float2 vB = make_float2(acc[mf][nf][2] + bB, acc[mf][nf][3] + bB);
            if (stats) {
                s += vA.x + vA.y + vB.x + vB.y;
                q += vA.x*vA.x + vA.y*vA.y + vB.x*vB.x + vB.y*vB.y;
            }
            if (relu) {
                vA.x = fmaxf(vA.x, 0.f); vA.y = fmaxf(vA.y, 0.f);
                vB.x = fmaxf(vB.x, 0.f); vB.y = fmaxf(vB.y, 0.f);
            }
            if (out16) {
                __half* pA = out16 + ((size_t)nB * C_ + rowA) * T_ + t0;
                __half* pB = out16 + ((size_t)nB * C_ + rowB) * T_ + t0;
                *reinterpret_cast<__half2*>(pA + col) = __floats2half2_rn(vA.x, vA.y);
                *reinterpret_cast<__half2*>(pB + col) = __floats2half2_rn(vB.x, vB.y);
            } else {
                float* pA = out32 + ((size_t)nB * C_ + rowA) * T_ + t0;
                float* pB = out32 + ((size_t)nB * C_ + rowB) * T_ + t0;
                *reinterpret_cast<float2*>(pA + col) = vA;
                *reinterpret_cast<float2*>(pB + col) = vB;
            }
        }
        if (stats) {
            #pragma unroll
            for (int d = 16; d > 0; d >>= 1) {
                s += __shfl_xor_sync(0xffffffffu, s, d);
                q += __shfl_xor_sync(0xffffffffu, q, d);
            }
            if (lane == 0) { ws[wid][mf][0] = s; ws[wid][mf][1] = q; }
        }
    }
    if (stats) {
        __syncthreads();
        if (tid < 8) {
            int mw = tid >> 1, mf = tid & 1;
            float s = ws[mw*2+0][mf][0] + ws[mw*2+1][mf][0];
            float q = ws[mw*2+0][mf][1] + ws[mw*2+1][mf][1];
            int g = o0 / 16 + tid;
            g_psum[nB][g][blockIdx.x]   = s;
            g_psumsq[nB][g][blockIdx.x] = q;
        }
    }
}

// ---------------- finalize GroupNorm stats (spread over 8 blocks) ----------------
__global__ void gn_finalize_kernel() {
    int idx = blockIdx.x * blockDim.x + threadIdx.x;
    if (idx >= N_ * G_) return;
    int n = idx / G_, g = idx % G_;
    float s = 0.f, q = 0.f;
    #pragma unroll
    for (int b = 0; b < NTB; b++) { s += g_psum[n][g][b]; q += g_psumsq[n][g][b]; }
    const float M = 16.f * T_;
    float m = s / M;
    float var = q / M - m * m;
    g_mean[idx] = m;
    g_rstd[idx] = rsqrtf(var + EPS_);
}

// ---------------- normalize+relu -> hT fp16 (transposed), reads g_h16 ----------------
__global__ __launch_bounds__(256) void norm_t_kernel(const float* __restrict__ gamma,
                                                     const float* __restrict__ beta) {
    __shared__ float st[64][65];
    int n = blockIdx.z, c0 = blockIdx.y * 64, t0 = blockIdx.x * 64;
    for (int i = threadIdx.x; i < 64 * 64; i += 256) {
        int ci = i >> 6, t = i & 63;
        int c = c0 + ci;
        float v = __half2float(g_h16[((size_t)n * C_ + c) * T_ + t0 + t]);
        int gi = n * G_ + (c >> 4);
        v = fmaxf((v - g_mean[gi]) * g_rstd[gi] * gamma[c] + beta[c], 0.f);
        st[ci][t] = v;
    }
    __syncthreads();
    for (int i = threadIdx.x; i < 64 * 64; i += 256) {
        int ci = i & 63, t = i >> 6;
        size_t dst = ((size_t)n * TPAD + 1 + t0 + t) * C_ + c0 + ci;
        g_hT[dst] = __float2half_rn(st[ci][t]);
    }
}

// ---------------- bilinear sampling -> S0/S2 fp16 (reads hT, vectorized) ----------------
__global__ __launch_bounds__(256) void sample_kernel(const float* __restrict__ locs,
                                                     const int* __restrict__ stride_p) {
    const int n = blockIdx.y;
    int sv = *stride_p;
    float fs = (sv > 0 && sv < 1000000) ? (float)sv : __int_as_float(sv);

    const int ci2 = threadIdx.x;   // half2 index: channels 2*ci2, 2*ci2+1

    #pragma unroll
    for (int tt = 0; tt < 4; tt++) {
        int t = blockIdx.x * 4 + tt;
        float y1 = locs[((size_t)n * 2 + 0) * T_ + t] / fs;
        float y2 = locs[((size_t)n * 2 + 1) * T_ + t] / fs;

        float pos0 = (float)t - 1.0f - y1;
        float f0 = floorf(pos0);
        float wb0 = pos0 - f0;
        int i00 = (int)f0, i01 = i00 + 1;
        float m00 = (i00 >= 0 && i00 < T_) ? 1.f : 0.f;
        float m01 = (i01 >= 0 && i01 < T_) ? 1.f : 0.f;
        size_t r00 = ((size_t)n * TPAD + 1 + min(max(i00, 0), T_ - 1)) * C_;
        size_t r01 = ((size_t)n * TPAD + 1 + min(max(i01, 0), T_ - 1)) * C_;

        float pos2 = (float)t + 1.0f + y2;
        float f2 = floorf(pos2);
        float wb2 = pos2 - f2;
        int i20 = (int)f2, i21 = i20 + 1;
        float m20 = (i20 >= 0 && i20 < T_) ? 1.f : 0.f;
        float m21 = (i21 >= 0 && i21 < T_) ? 1.f : 0.f;
        size_t r20 = ((size_t)n * TPAD + 1 + min(max(i20, 0), T_ - 1)) * C_;
        size_t r21 = ((size_t)n * TPAD + 1 + min(max(i21, 0), T_ - 1)) * C_;

        size_t dst = ((size_t)n * TPAD + 1 + t) * C_;

        __half2 a0 = ((const __half2*)(g_hT + r00))[ci2];
        __half2 b0 = ((const __half2*)(g_hT + r01))[ci2];
        __half2 a2 = ((const __half2*)(g_hT + r20))[ci2];
        __half2 b2 = ((const __half2*)(g_hT + r21))[ci2];

        float w0a = (1.f - wb0) * m00, w0b = wb0 * m01;
        float w2a = (1.f - wb2) * m20, w2b = wb2 * m21;

        float s0x = __half2float(a0.x) * w0a + __half2float(b0.x) * w0b;
        float s0y = __half2float(a0.y) * w0a + __half2float(b0.y) * w0b;
        float s2x = __half2float(a2.x) * w2a + __half2float(b2.x) * w2b;
        float s2y = __half2float(a2.y) * w2a + __half2float(b2.y) * w2b;

        ((__half2*)(g_S0 + dst))[ci2] = __floats2half2_rn(s0x, s0y);
        ((__half2*)(g_S2 + dst))[ci2] = __floats2half2_rn(s2x, s2y);
    }
}

// ---------------- final 512->2 conv (parallel over t and channel groups) ----------------
__global__ __launch_bounds__(256) void outconv_kernel(const float* __restrict__ W,
                                                      const float* __restrict__ b,
                                                      const float* __restrict__ feat,
                                                      float* __restrict__ out) {
    __shared__ float sW[2 * C_ * 3];
    __shared__ float red[4][64][2];
    for (int l = threadIdx.x; l < 2 * C_ * 3; l += 256) sW[l] = W[l];
    __syncthreads();

    const int tl = threadIdx.x & 63;
    const int cg = threadIdx.x >> 6;           // 0..3
    const int t = blockIdx.x * 64 + tl;
    const int n = blockIdx.y;
    const float* fb = feat + (size_t)n * C_ * T_;
    float a0 = 0.f, a1 = 0.f;
    bool lok = (t >= 1), rok = (t < T_ - 1);
    const int c0 = cg * 128;
    for (int i = c0; i < c0 + 128; i++) {
        const float* fr = fb + (size_t)i * T_ + t;
        float vm = lok ? fr[-1] : 0.0f;
        float v0 = fr[0];
        float vp = rok ? fr[1] : 0.0f;
        a0 = fmaf(sW[i*3+0], vm, a0);
        a0 = fmaf(sW[i*3+1], v0, a0);
        a0 = fmaf(sW[i*3+2], vp, a0);
        a1 = fmaf(sW[(C_+i)*3+0], vm, a1);
        a1 = fmaf(sW[(C_+i)*3+1], v0, a1);
        a1 = fmaf(sW[(C_+i)*3+2], vp, a1);
    }
    red[cg][tl][0] = a0;
    red[cg][tl][1] = a1;
    __syncthreads();
    if (cg == 0) {
        float r0 = b[0] + red[0][tl][0] + red[1][tl][0] + red[2][tl][0] + red[3][tl][0];
        float r1 = b[1] + red[0][tl][1] + red[1][tl][1] + red[2][tl][1] + red[3][tl][1];
        out[(size_t)n * 2 * T_ + t]       = r0;
        out[((size_t)n * 2 + 1) * T_ + t] = r1;
    }
}

// ---------------------------------------------------------------------------
extern "C" void kernel_launch(void* const* d_in, const int* in_sizes, int n_in,
                              void* d_out, int out_size) {
    const float* feat   = (const float*)d_in[0];
    const float* locs   = (const float*)d_in[1];
    const float* conv_w = (const float*)d_in[2];
    const float* conv_b = (const float*)d_in[3];
    const float* gn_g   = (const float*)d_in[4];
    const float* gn_b   = (const float*)d_in[5];
    const float* dcn_w  = (const float*)d_in[6];
    const float* dcn_b  = (const float*)d_in[7];
    const float* out_w  = (const float*)d_in[8];
    const float* out_b  = (const float*)d_in[9];
    const int*   stride = (const int*)d_in[10];

    float* out      = (float*)d_out;
    float* out_feat = (float*)d_out + OFFSET_ELEMS;

    __half *w1, *w2, *xt, *ht, *s0, *s2, *hbuf16;
    cudaGetSymbolAddress((void**)&w1, g_W);  w2 = w1 + 3*C_*C_;
    cudaGetSymbolAddress((void**)&xt, g_xT);
    cudaGetSymbolAddress((void**)&ht, g_hT);
    cudaGetSymbolAddress((void**)&s0, g_S0);
    cudaGetSymbolAddress((void**)&s2, g_S2);
    cudaGetSymbolAddress((void**)&hbuf16, g_h16);

    const int SMEM_BYTES = STAGES * STAGE_BYTES;   // 96 KB
    cudaFuncSetAttribute(gemm_kernel, cudaFuncAttributeMaxDynamicSharedMemorySize, SMEM_BYTES);

    dim3 tr_grid(T_/64, C_/64, N_);
    dim3 gemm_grid(T_/TNT, C_/TMT, N_);   // (32, 4, 8) = 1024

    prep_w_kernel<<<dim3(512, 2), 256>>>(conv_w, dcn_w);
    prep_x_kernel<<<tr_grid, 256>>>(feat);
    zero_guard_kernel<<<(N_*C_ + 255)/256, 256>>>();
    gemm_kernel<<<gemm_grid, 256, SMEM_BYTES>>>(w1,
        xt, xt, xt, -1, 0, 1, conv_b, nullptr, hbuf16, 0, 1);
    gn_finalize_kernel<<<8, 32>>>();
    norm_t_kernel<<<tr_grid, 256>>>(gn_g, gn_b);
    sample_kernel<<<dim3(T_/4, N_), 256>>>(locs, stride);
    gemm_kernel<<<gemm_grid, 256, SMEM_BYTES>>>(w2,
        s0, ht, s2, 0, 0, 0, dcn_b, out_feat, nullptr, 1, 0);
    outconv_kernel<<<dim3(T_/64, N_), 256>>>(out_w, out_b, out_feat, out);
}

// round 15
// speedup vs baseline: 1.4206x; 1.0316x over previous
#include <cuda_runtime.h>
#include <cuda_fp16.h>
#include <cstdint>
#include <math.h>

#define N_  8
#define C_  512
#define T_  4096
#define TPAD (T_+2)
#define G_  32
#define EPS_ 1e-5f
#define OFFSET_ELEMS (N_*2*T_)

#define TMT 128
#define TNT 128
#define NCHUNK 24   // 3 taps * (512/64)
#define STAGES 3
#define STAGE_BYTES 32768   // A 16K | B 16K
#define NTB (T_/TNT)        // 32 t-blocks

// ---------------- device scratch ----------------
__device__ __half g_h16[(size_t)N_*C_*T_];       // conv1 raw output fp16 [n][c][t]
__device__ float g_mean[N_*G_], g_rstd[N_*G_];
__device__ float g_psum[N_][G_][NTB], g_psumsq[N_][G_][NTB];
// weights: [conv][tap][o][ci] fp16
__device__ __half g_W[2][3*C_*C_];
// T-major activation planes, padded rows [n][TPAD][C] (rows 0 and TPAD-1 are guards)
__device__ __half g_xT[(size_t)N_*TPAD*C_];
__device__ __half g_hT[(size_t)N_*TPAD*C_];
__device__ __half g_S0[(size_t)N_*TPAD*C_];
__device__ __half g_S2[(size_t)N_*TPAD*C_];

// ---------------- PTX helpers ----------------
__device__ __forceinline__ uint32_t smem_u32(const void* p) {
    uint32_t a;
    asm("{ .reg .u64 t; cvta.to.shared.u64 t, %1; cvt.u32.u64 %0, t; }" : "=r"(a) : "l"(p));
    return a;
}
__device__ __forceinline__ void cp_async16(uint32_t saddr, const void* gaddr) {
    asm volatile("cp.async.cg.shared.global [%0], [%1], 16;" :: "r"(saddr), "l"(gaddr));
}
__device__ __forceinline__ void ldsm4(uint32_t* r, uint32_t addr) {
    asm volatile("ldmatrix.sync.aligned.m8n8.x4.shared.b16 {%0,%1,%2,%3}, [%4];"
        : "=r"(r[0]), "=r"(r[1]), "=r"(r[2]), "=r"(r[3]) : "r"(addr));
}
__device__ __forceinline__ void mma_f32(float* d, const uint32_t* a, uint32_t b0, uint32_t b1) {
    asm volatile("mma.sync.aligned.m16n8k16.row.col.f32.f16.f16.f32 "
        "{%0,%1,%2,%3}, {%4,%5,%6,%7}, {%8,%9}, {%0,%1,%2,%3};"
        : "+f"(d[0]), "+f"(d[1]), "+f"(d[2]), "+f"(d[3])
        : "r"(a[0]), "r"(a[1]), "r"(a[2]), "r"(a[3]), "r"(b0), "r"(b1));
}

// ---------------- prep: weights -> fp16, [tap][o][ci] ----------------
__global__ __launch_bounds__(256) void prep_w_kernel(const float* __restrict__ w1,
                                                     const float* __restrict__ w2) {
    const int conv = blockIdx.y;
    const float* w = conv ? w2 : w1;
    __half* W = g_W[conv];
    const int total = 3 * C_ * C_;
    for (int idx = blockIdx.x * 256 + threadIdx.x; idx < total; idx += gridDim.x * 256) {
        int k = idx / (C_ * C_);
        int rem = idx % (C_ * C_);
        int o = rem / C_, ci = rem % C_;
        W[idx] = __float2half_rn(w[((size_t)o * C_ + ci) * 3 + k]);
    }
}

// ---------------- prep: feat [n][c][t] -> xT fp16 [n][1+t][c] ----------------
__global__ __launch_bounds__(256) void prep_x_kernel(const float* __restrict__ feat) {
    __shared__ float sx[64][65];
    int n = blockIdx.z, c0 = blockIdx.y * 64, t0 = blockIdx.x * 64;
    const float* xb = feat + ((size_t)n * C_ + c0) * T_ + t0;
    for (int i = threadIdx.x; i < 64 * 64; i += 256) {
        int ci = i >> 6, t = i & 63;
        sx[ci][t] = xb[(size_t)ci * T_ + t];
    }
    __syncthreads();
    for (int i = threadIdx.x; i < 64 * 64; i += 256) {
        int ci = i & 63, t = i >> 6;
        size_t dst = ((size_t)n * TPAD + 1 + t0 + t) * C_ + c0 + ci;
        g_xT[dst] = __float2half_rn(sx[ci][t]);
    }
}

__global__ __launch_bounds__(256) void zero_guard_kernel() {
    int idx = blockIdx.x * 256 + threadIdx.x;      // over N_*C_
    if (idx >= N_ * C_) return;
    int n = idx / C_, ci = idx % C_;
    size_t r0 = ((size_t)n * TPAD) * C_ + ci;
    size_t r1 = ((size_t)n * TPAD + TPAD - 1) * C_ + ci;
    __half z = __float2half_rn(0.f);
    g_xT[r0] = z; g_xT[r1] = z;
}

// ---------------- fp16 MMA GEMM (128x128 tile, warp 32x64, 3 stages) ----------------
extern __shared__ char smem_raw[];
__global__ __launch_bounds__(256) void gemm_kernel(
    const __half* __restrict__ W,
    const __half* __restrict__ B0, const __half* __restrict__ B1, const __half* __restrict__ B2,
    int r0off, int r1off, int r2off,
    const float* __restrict__ bias, float* __restrict__ out32, __half* __restrict__ out16,
    int relu, int stats)
{
    const int tid = threadIdx.x, lane = tid & 31, wid = tid >> 5;
    const int nB = blockIdx.z, o0 = blockIdx.y * TMT, t0 = blockIdx.x * TNT;

    const uint32_t sb = smem_u32(smem_raw);

    // warp tile: 32 rows (m) x 64 cols (n); 4 m-warps x 2 n-warps
    const int m0 = (wid >> 1) * 32;
    const int nw = (wid & 1) * 64;
    const int arow = lane & 15, acb = lane >> 4;
    const int brow = (lane & 7) + ((lane >> 4) << 3), bcb = (lane >> 3) & 1;
    uint32_t aoff[2], a7[2], boff[4], b7[4];
    #pragma unroll
    for (int mf = 0; mf < 2; mf++) {
        int r = m0 + mf * 16 + arow;
        aoff[mf] = (uint32_t)(r * 128); a7[mf] = (uint32_t)(r & 7);
    }
    #pragma unroll
    for (int p = 0; p < 4; p++) {
        int r = nw + p * 16 + brow;
        boff[p] = (uint32_t)(r * 128); b7[p] = (uint32_t)(r & 7);
    }

    // hoisted loader indices (loop-invariant per thread)
    int lrow[4], lq[4]; uint32_t lso[4];
    #pragma unroll
    for (int it = 0; it < 4; it++) {
        int i = tid + it * 256;
        lrow[it] = i >> 3; lq[it] = i & 7;
        lso[it] = (uint32_t)(lrow[it] * 128 + ((lq[it] ^ (lrow[it] & 7)) << 4));
    }

    float acc[2][8][4];
    #pragma unroll
    for (int a = 0; a < 2; a++)
        #pragma unroll
        for (int b = 0; b < 8; b++)
            #pragma unroll
            for (int c = 0; c < 4; c++) acc[a][b][c] = 0.f;

    auto load_chunk = [&](int c, int s) {
        const int tap = c >> 3, ci0 = (c & 7) * 64;
        const __half* bsrc; int ro;
        if (tap == 0)      { bsrc = B0; ro = r0off; }
        else if (tap == 1) { bsrc = B1; ro = r1off; }
        else               { bsrc = B2; ro = r2off; }
        const size_t brow0 = (size_t)nB * TPAD + 1 + t0 + ro;
        const __half* wsrc = W + ((size_t)tap * C_ + o0) * C_ + ci0;
        const uint32_t st = sb + (uint32_t)s * (uint32_t)STAGE_BYTES;
        #pragma unroll
        for (int it = 0; it < 4; it++)
            cp_async16(st + lso[it], wsrc + (size_t)lrow[it] * C_ + lq[it] * 8);
        #pragma unroll
        for (int it = 0; it < 4; it++)
            cp_async16(st + 16384u + lso[it], bsrc + (brow0 + lrow[it]) * C_ + ci0 + lq[it] * 8);
        asm volatile("cp.async.commit_group;" ::: "memory");
    };

    auto compute = [&](int s) {
        const uint32_t Ab = sb + (uint32_t)s * (uint32_t)STAGE_BYTES;
        const uint32_t Bb = Ab + 16384u;
        #pragma unroll
        for (int ks = 0; ks < 4; ks++) {
            uint32_t ah[2][4], bhv[4][4];
            #pragma unroll
            for (int mf = 0; mf < 2; mf++) {
                uint32_t off = aoff[mf] + ((((uint32_t)(2*ks) + acb) ^ a7[mf]) << 4);
                ldsm4(ah[mf], Ab + off);
            }
            #pragma unroll
            for (int p = 0; p < 4; p++) {
                uint32_t off = boff[p] + ((((uint32_t)(2*ks) + bcb) ^ b7[p]) << 4);
                ldsm4(bhv[p], Bb + off);
            }
            #pragma unroll
            for (int mf = 0; mf < 2; mf++) {
                #pragma unroll
                for (int nf = 0; nf < 8; nf++) {
                    int p = nf >> 1, j = (nf & 1) * 2;
                    mma_f32(acc[mf][nf], ah[mf], bhv[p][j], bhv[p][j+1]);
                }
            }
        }
    };

    // 3-stage pipeline, single barrier per chunk, compute-before-prefetch:
    // iter c: wait(chunk c) -> sync -> compute(c) -> prefetch(c+2)
    load_chunk(0, 0);
    load_chunk(1, 1);
    for (int c = 0; c < NCHUNK; c++) {
        if (c >= NCHUNK - 2) asm volatile("cp.async.wait_group 0;" ::: "memory");
        else                 asm volatile("cp.async.wait_group 1;" ::: "memory");
        __syncthreads();
        compute(c % STAGES);
        if (c + 2 < NCHUNK) load_chunk(c + 2, (c + 2) % STAGES);
    }

    // epilogue (+ optional fused GroupNorm partial stats, deterministic)
    __shared__ float ws[8][2][2];
    #pragma unroll
    for (int mf = 0; mf < 2; mf++) {
        int rowA = o0 + m0 + mf * 16 + (lane >> 2);
        int rowB = rowA + 8;
        float bA = bias[rowA], bB = bias[rowB];
        float s = 0.f, q = 0.f;
        #pragma unroll
        for (int nf = 0; nf < 8; nf++) {
            int col = nw + nf * 8 + (lane & 3) * 2;
            float2 vA = make_float2(acc[mf][nf][0] + bA, acc[mf][nf][1] + bA);
            float2 vB = make_float2(acc[mf][nf][2] + bB, acc[mf][nf][3] + bB);
            if (stats) {
                s += vA.x + vA.y + vB.x + vB.y;
                q += vA.x*vA.x + vA.y*vA.y + vB.x*vB.x + vB.y*vB.y;
            }
            if (relu) {
                vA.x = fmaxf(vA.x, 0.f); vA.y = fmaxf(vA.y, 0.f);
                vB.x = fmaxf(vB.x, 0.f); vB.y = fmaxf(vB.y, 0.f);
            }
            if (out16) {
                __half* pA = out16 + ((size_t)nB * C_ + rowA) * T_ + t0;
                __half* pB = out16 + ((size_t)nB * C_ + rowB) * T_ + t0;
                *reinterpret_cast<__half2*>(pA + col) = __floats2half2_rn(vA.x, vA.y);
                *reinterpret_cast<__half2*>(pB + col) = __floats2half2_rn(vB.x, vB.y);
            } else {
                float* pA = out32 + ((size_t)nB * C_ + rowA) * T_ + t0;
                float* pB = out32 + ((size_t)nB * C_ + rowB) * T_ + t0;
                *reinterpret_cast<float2*>(pA + col) = vA;
                *reinterpret_cast<float2*>(pB + col) = vB;
            }
        }
        if (stats) {
            #pragma unroll
            for (int d = 16; d > 0; d >>= 1) {
                s += __shfl_xor_sync(0xffffffffu, s, d);
                q += __shfl_xor_sync(0xffffffffu, q, d);
            }
            if (lane == 0) { ws[wid][mf][0] = s; ws[wid][mf][1] = q; }
        }
    }
    if (stats) {
        __syncthreads();
        if (tid < 8) {
            int mw = tid >> 1, mf = tid & 1;
            float s = ws[mw*2+0][mf][0] + ws[mw*2+1][mf][0];
            float q = ws[mw*2+0][mf][1] + ws[mw*2+1][mf][1];
            int g = o0 / 16 + tid;
            g_psum[nB][g][blockIdx.x]   = s;
            g_psumsq[nB][g][blockIdx.x] = q;
        }
    }
}

// ---------------- finalize GroupNorm stats (spread over 8 blocks) ----------------
__global__ void gn_finalize_kernel() {
    int idx = blockIdx.x * blockDim.x + threadIdx.x;
    if (idx >= N_ * G_) return;
    int n = idx / G_, g = idx % G_;
    float s = 0.f, q = 0.f;
    #pragma unroll
    for (int b = 0; b < NTB; b++) { s += g_psum[n][g][b]; q += g_psumsq[n][g][b]; }
    const float M = 16.f * T_;
    float m = s / M;
    float var = q / M - m * m;
    g_mean[idx] = m;
    g_rstd[idx] = rsqrtf(var + EPS_);
}

// ---------------- normalize+relu -> hT fp16 (transposed), reads g_h16 ----------------
__global__ __launch_bounds__(256) void norm_t_kernel(const float* __restrict__ gamma,
                                                     const float* __restrict__ beta) {
    __shared__ float st[64][65];
    int n = blockIdx.z, c0 = blockIdx.y * 64, t0 = blockIdx.x * 64;
    for (int i = threadIdx.x; i < 64 * 64; i += 256) {
        int ci = i >> 6, t = i & 63;
        int c = c0 + ci;
        float v = __half2float(g_h16[((size_t)n * C_ + c) * T_ + t0 + t]);
        int gi = n * G_ + (c >> 4);
        v = fmaxf((v - g_mean[gi]) * g_rstd[gi] * gamma[c] + beta[c], 0.f);
        st[ci][t] = v;
    }
    __syncthreads();
    for (int i = threadIdx.x; i < 64 * 64; i += 256) {
        int ci = i & 63, t = i >> 6;
        size_t dst = ((size_t)n * TPAD + 1 + t0 + t) * C_ + c0 + ci;
        g_hT[dst] = __float2half_rn(st[ci][t]);
    }
}

// ---------------- bilinear sampling -> S0/S2 fp16 (reads hT, vectorized) ----------------
__global__ __launch_bounds__(256) void sample_kernel(const float* __restrict__ locs,
                                                     const int* __restrict__ stride_p) {
    const int n = blockIdx.y;
    int sv = *stride_p;
    float fs = (sv > 0 && sv < 1000000) ? (float)sv : __int_as_float(sv);

    const int ci2 = threadIdx.x;   // half2 index: channels 2*ci2, 2*ci2+1

    #pragma unroll
    for (int tt = 0; tt < 4; tt++) {
        int t = blockIdx.x * 4 + tt;
        float y1 = locs[((size_t)n * 2 + 0) * T_ + t] / fs;
        float y2 = locs[((size_t)n * 2 + 1) * T_ + t] / fs;

        float pos0 = (float)t - 1.0f - y1;
        float f0 = floorf(pos0);
        float wb0 = pos0 - f0;
        int i00 = (int)f0, i01 = i00 + 1;
        float m00 = (i00 >= 0 && i00 < T_) ? 1.f : 0.f;
        float m01 = (i01 >= 0 && i01 < T_) ? 1.f : 0.f;
        size_t r00 = ((size_t)n * TPAD + 1 + min(max(i00, 0), T_ - 1)) * C_;
        size_t r01 = ((size_t)n * TPAD + 1 + min(max(i01, 0), T_ - 1)) * C_;

        float pos2 = (float)t + 1.0f + y2;
        float f2 = floorf(pos2);
        float wb2 = pos2 - f2;
        int i20 = (int)f2, i21 = i20 + 1;
        float m20 = (i20 >= 0 && i20 < T_) ? 1.f : 0.f;
        float m21 = (i21 >= 0 && i21 < T_) ? 1.f : 0.f;
        size_t r20 = ((size_t)n * TPAD + 1 + min(max(i20, 0), T_ - 1)) * C_;
        size_t r21 = ((size_t)n * TPAD + 1 + min(max(i21, 0), T_ - 1)) * C_;

        size_t dst = ((size_t)n * TPAD + 1 + t) * C_;

        __half2 a0 = ((const __half2*)(g_hT + r00))[ci2];
        __half2 b0 = ((const __half2*)(g_hT + r01))[ci2];
        __half2 a2 = ((const __half2*)(g_hT + r20))[ci2];
        __half2 b2 = ((const __half2*)(g_hT + r21))[ci2];

        float w0a = (1.f - wb0) * m00, w0b = wb0 * m01;
        float w2a = (1.f - wb2) * m20, w2b = wb2 * m21;

        float s0x = __half2float(a0.x) * w0a + __half2float(b0.x) * w0b;
        float s0y = __half2float(a0.y) * w0a + __half2float(b0.y) * w0b;
        float s2x = __half2float(a2.x) * w2a + __half2float(b2.x) * w2b;
        float s2y = __half2float(a2.y) * w2a + __half2float(b2.y) * w2b;

        ((__half2*)(g_S0 + dst))[ci2] = __floats2half2_rn(s0x, s0y);
        ((__half2*)(g_S2 + dst))[ci2] = __floats2half2_rn(s2x, s2y);
    }
}

// ---------------- final 512->2 conv (parallel over t and channel groups) ----------------
__global__ __launch_bounds__(256) void outconv_kernel(const float* __restrict__ W,
                                                      const float* __restrict__ b,
                                                      const float* __restrict__ feat,
                                                      float* __restrict__ out) {
    __shared__ float sW[2 * C_ * 3];
    __shared__ float red[4][64][2];
    for (int l = threadIdx.x; l < 2 * C_ * 3; l += 256) sW[l] = W[l];
    __syncthreads();

    const int tl = threadIdx.x & 63;
    const int cg = threadIdx.x >> 6;           // 0..3
    const int t = blockIdx.x * 64 + tl;
    const int n = blockIdx.y;
    const float* fb = feat + (size_t)n * C_ * T_;
    float a0 = 0.f, a1 = 0.f;
    bool lok = (t >= 1), rok = (t < T_ - 1);
    const int c0 = cg * 128;
    for (int i = c0; i < c0 + 128; i++) {
        const float* fr = fb + (size_t)i * T_ + t;
        float vm = lok ? fr[-1] : 0.0f;
        float v0 = fr[0];
        float vp = rok ? fr[1] : 0.0f;
        a0 = fmaf(sW[i*3+0], vm, a0);
        a0 = fmaf(sW[i*3+1], v0, a0);
        a0 = fmaf(sW[i*3+2], vp, a0);
        a1 = fmaf(sW[(C_+i)*3+0], vm, a1);
        a1 = fmaf(sW[(C_+i)*3+1], v0, a1);
        a1 = fmaf(sW[(C_+i)*3+2], vp, a1);
    }
    red[cg][tl][0] = a0;
    red[cg][tl][1] = a1;
    __syncthreads();
    if (cg == 0) {
        float r0 = b[0] + red[0][tl][0] + red[1][tl][0] + red[2][tl][0] + red[3][tl][0];
        float r1 = b[1] + red[0][tl][1] + red[1][tl][1] + red[2][tl][1] + red[3][tl][1];
        out[(size_t)n * 2 * T_ + t]       = r0;
        out[((size_t)n * 2 + 1) * T_ + t] = r1;
    }
}

// ---------------------------------------------------------------------------
extern "C" void kernel_launch(void* const* d_in, const int* in_sizes, int n_in,
                              void* d_out, int out_size) {
    const float* feat   = (const float*)d_in[0];
    const float* locs   = (const float*)d_in[1];
    const float* conv_w = (const float*)d_in[2];
    const float* conv_b = (const float*)d_in[3];
    const float* gn_g   = (const float*)d_in[4];
    const float* gn_b   = (const float*)d_in[5];
    const float* dcn_w  = (const float*)d_in[6];
    const float* dcn_b  = (const float*)d_in[7];
    const float* out_w  = (const float*)d_in[8];
    const float* out_b  = (const float*)d_in[9];
    const int*   stride = (const int*)d_in[10];

    float* out      = (float*)d_out;
    float* out_feat = (float*)d_out + OFFSET_ELEMS;

    __half *w1, *w2, *xt, *ht, *s0, *s2, *hbuf16;
    cudaGetSymbolAddress((void**)&w1, g_W);  w2 = w1 + 3*C_*C_;
    cudaGetSymbolAddress((void**)&xt, g_xT);
    cudaGetSymbolAddress((void**)&ht, g_hT);
    cudaGetSymbolAddress((void**)&s0, g_S0);
    cudaGetSymbolAddress((void**)&s2, g_S2);
    cudaGetSymbolAddress((void**)&hbuf16, g_h16);

    const int SMEM_BYTES = STAGES * STAGE_BYTES;   // 96 KB
    cudaFuncSetAttribute(gemm_kernel, cudaFuncAttributeMaxDynamicSharedMemorySize, SMEM_BYTES);

    dim3 tr_grid(T_/64, C_/64, N_);
    dim3 gemm_grid(T_/TNT, C_/TMT, N_);   // (32, 4, 8) = 1024

    prep_w_kernel<<<dim3(512, 2), 256>>>(conv_w, dcn_w);
    prep_x_kernel<<<tr_grid, 256>>>(feat);
    zero_guard_kernel<<<(N_*C_ + 255)/256, 256>>>();
    gemm_kernel<<<gemm_grid, 256, SMEM_BYTES>>>(w1,
        xt, xt, xt, -1, 0, 1, conv_b, nullptr, hbuf16, 0, 1);
    gn_finalize_kernel<<<8, 32>>>();
    norm_t_kernel<<<tr_grid, 256>>>(gn_g, gn_b);
    sample_kernel<<<dim3(T_/4, N_), 256>>>(locs, stride);
    gemm_kernel<<<gemm_grid, 256, SMEM_BYTES>>>(w2,
        s0, ht, s2, 0, 0, 0, dcn_b, out_feat, nullptr, 1, 0);
    outconv_kernel<<<dim3(T_/64, N_), 256>>>(out_w, out_b, out_feat, out);
}

// round 16
// speedup vs baseline: 1.5831x; 1.1145x over previous
#include <cuda_runtime.h>
#include <cuda_fp16.h>
#include <cstdint>
#include <math.h>

#define N_  8
#define C_  512
#define T_  4096
#define TPAD (T_+2)
#define G_  32
#define EPS_ 1e-5f
#define OFFSET_ELEMS (N_*2*T_)

#define TMT 128
#define TNT 128
#define NCHUNK 24   // 3 taps * (512/64)
#define STAGES 3
#define STAGE_BYTES 32768   // A 16K | B 16K
#define NTB (T_/TNT)        // 32 t-blocks

// ---------------- device scratch ----------------
__device__ __half g_h16[(size_t)N_*C_*T_];       // conv1 raw output fp16 [n][c][t]
__device__ float g_mean[N_*G_], g_rstd[N_*G_];
__device__ float g_psum[N_][G_][NTB], g_psumsq[N_][G_][NTB];
__device__ float g_ocp[N_][4][2][NTB][130];      // fused outconv partials (halo slots)
// weights: [conv][tap][o][ci] fp16
__device__ __half g_W[2][3*C_*C_];
// T-major activation planes, padded rows [n][TPAD][C] (rows 0 and TPAD-1 are guards)
__device__ __half g_xT[(size_t)N_*TPAD*C_];
__device__ __half g_hT[(size_t)N_*TPAD*C_];
__device__ __half g_S0[(size_t)N_*TPAD*C_];
__device__ __half g_S2[(size_t)N_*TPAD*C_];

// ---------------- PTX helpers ----------------
__device__ __forceinline__ uint32_t smem_u32(const void* p) {
    uint32_t a;
    asm("{ .reg .u64 t; cvta.to.shared.u64 t, %1; cvt.u32.u64 %0, t; }" : "=r"(a) : "l"(p));
    return a;
}
__device__ __forceinline__ void cp_async16(uint32_t saddr, const void* gaddr) {
    asm volatile("cp.async.cg.shared.global [%0], [%1], 16;" :: "r"(saddr), "l"(gaddr));
}
__device__ __forceinline__ void ldsm4(uint32_t* r, uint32_t addr) {
    asm volatile("ldmatrix.sync.aligned.m8n8.x4.shared.b16 {%0,%1,%2,%3}, [%4];"
        : "=r"(r[0]), "=r"(r[1]), "=r"(r[2]), "=r"(r[3]) : "r"(addr));
}
__device__ __forceinline__ void mma_f32(float* d, const uint32_t* a, uint32_t b0, uint32_t b1) {
    asm volatile("mma.sync.aligned.m16n8k16.row.col.f32.f16.f16.f32 "
        "{%0,%1,%2,%3}, {%4,%5,%6,%7}, {%8,%9}, {%0,%1,%2,%3};"
        : "+f"(d[0]), "+f"(d[1]), "+f"(d[2]), "+f"(d[3])
        : "r"(a[0]), "r"(a[1]), "r"(a[2]), "r"(a[3]), "r"(b0), "r"(b1));
}

// ---------------- prep: weights -> fp16, [tap][o][ci] ----------------
__global__ __launch_bounds__(256) void prep_w_kernel(const float* __restrict__ w1,
                                                     const float* __restrict__ w2) {
    const int conv = blockIdx.y;
    const float* w = conv ? w2 : w1;
    __half* W = g_W[conv];
    const int total = 3 * C_ * C_;
    for (int idx = blockIdx.x * 256 + threadIdx.x; idx < total; idx += gridDim.x * 256) {
        int k = idx / (C_ * C_);
        int rem = idx % (C_ * C_);
        int o = rem / C_, ci = rem % C_;
        W[idx] = __float2half_rn(w[((size_t)o * C_ + ci) * 3 + k]);
    }
}

// ---------------- prep: feat [n][c][t] -> xT fp16 [n][1+t][c] ----------------
__global__ __launch_bounds__(256) void prep_x_kernel(const float* __restrict__ feat) {
    __shared__ float sx[64][65];
    int n = blockIdx.z, c0 = blockIdx.y * 64, t0 = blockIdx.x * 64;
    const float* xb = feat + ((size_t)n * C_ + c0) * T_ + t0;
    for (int i = threadIdx.x; i < 64 * 64; i += 256) {
        int ci = i >> 6, t = i & 63;
        sx[ci][t] = xb[(size_t)ci * T_ + t];
    }
    __syncthreads();
    for (int i = threadIdx.x; i < 64 * 64; i += 256) {
        int ci = i & 63, t = i >> 6;
        size_t dst = ((size_t)n * TPAD + 1 + t0 + t) * C_ + c0 + ci;
        g_xT[dst] = __float2half_rn(sx[ci][t]);
    }
}

__global__ __launch_bounds__(256) void zero_guard_kernel() {
    int idx = blockIdx.x * 256 + threadIdx.x;      // over N_*C_
    if (idx >= N_ * C_) return;
    int n = idx / C_, ci = idx % C_;
    size_t r0 = ((size_t)n * TPAD) * C_ + ci;
    size_t r1 = ((size_t)n * TPAD + TPAD - 1) * C_ + ci;
    __half z = __float2half_rn(0.f);
    g_xT[r0] = z; g_xT[r1] = z;
}

// ---------------- fp16 MMA GEMM (128x128 tile, warp 32x64, 3 stages) ----------------
// oc mode (ocw != nullptr): fused outconv partial sums written to g_ocp
extern __shared__ char smem_raw[];
__global__ __launch_bounds__(256, 2) void gemm_kernel(
    const __half* __restrict__ W,
    const __half* __restrict__ B0, const __half* __restrict__ B1, const __half* __restrict__ B2,
    int r0off, int r1off, int r2off,
    const float* __restrict__ bias, float* __restrict__ out32, __half* __restrict__ out16,
    const float* __restrict__ ocw, int relu, int stats)
{
    const int tid = threadIdx.x, lane = tid & 31, wid = tid >> 5;
    const int nB = blockIdx.z, o0 = blockIdx.y * TMT, t0 = blockIdx.x * TNT;

    const uint32_t sb = smem_u32(smem_raw);

    // warp tile: 32 rows (m) x 64 cols (n); 4 m-warps x 2 n-warps
    const int m0 = (wid >> 1) * 32;
    const int nw = (wid & 1) * 64;
    const int arow = lane & 15, acb = lane >> 4;
    const int brow = (lane & 7) + ((lane >> 4) << 3), bcb = (lane >> 3) & 1;
    uint32_t aoff[2], a7[2], boff[4], b7[4];
    #pragma unroll
    for (int mf = 0; mf < 2; mf++) {
        int r = m0 + mf * 16 + arow;
        aoff[mf] = (uint32_t)(r * 128); a7[mf] = (uint32_t)(r & 7);
    }
    #pragma unroll
    for (int p = 0; p < 4; p++) {
        int r = nw + p * 16 + brow;
        boff[p] = (uint32_t)(r * 128); b7[p] = (uint32_t)(r & 7);
    }

    // hoisted loader indices (loop-invariant per thread)
    int lrow[4], lq[4]; uint32_t lso[4];
    #pragma unroll
    for (int it = 0; it < 4; it++) {
        int i = tid + it * 256;
        lrow[it] = i >> 3; lq[it] = i & 7;
        lso[it] = (uint32_t)(lrow[it] * 128 + ((lq[it] ^ (lrow[it] & 7)) << 4));
    }

    float acc[2][8][4];
    #pragma unroll
    for (int a = 0; a < 2; a++)
        #pragma unroll
        for (int b = 0; b < 8; b++)
            #pragma unroll
            for (int c = 0; c < 4; c++) acc[a][b][c] = 0.f;

    auto load_chunk = [&](int c, int s) {
        const int tap = c >> 3, ci0 = (c & 7) * 64;
        const __half* bsrc; int ro;
        if (tap == 0)      { bsrc = B0; ro = r0off; }
        else if (tap == 1) { bsrc = B1; ro = r1off; }
        else               { bsrc = B2; ro = r2off; }
        const size_t brow0 = (size_t)nB * TPAD + 1 + t0 + ro;
        const __half* wsrc = W + ((size_t)tap * C_ + o0) * C_ + ci0;
        const uint32_t st = sb + (uint32_t)s * (uint32_t)STAGE_BYTES;
        #pragma unroll
        for (int it = 0; it < 4; it++)
            cp_async16(st + lso[it], wsrc + (size_t)lrow[it] * C_ + lq[it] * 8);
        #pragma unroll
        for (int it = 0; it < 4; it++)
            cp_async16(st + 16384u + lso[it], bsrc + (brow0 + lrow[it]) * C_ + ci0 + lq[it] * 8);
        asm volatile("cp.async.commit_group;" ::: "memory");
    };

    auto compute = [&](int s) {
        const uint32_t Ab = sb + (uint32_t)s * (uint32_t)STAGE_BYTES;
        const uint32_t Bb = Ab + 16384u;
        #pragma unroll
        for (int ks = 0; ks < 4; ks++) {
            uint32_t ah[2][4], bhv[4][4];
            #pragma unroll
            for (int mf = 0; mf < 2; mf++) {
                uint32_t off = aoff[mf] + ((((uint32_t)(2*ks) + acb) ^ a7[mf]) << 4);
                ldsm4(ah[mf], Ab + off);
            }
            #pragma unroll
            for (int p = 0; p < 4; p++) {
                uint32_t off = boff[p] + ((((uint32_t)(2*ks) + bcb) ^ b7[p]) << 4);
                ldsm4(bhv[p], Bb + off);
            }
            #pragma unroll
            for (int mf = 0; mf < 2; mf++) {
                #pragma unroll
                for (int nf = 0; nf < 8; nf++) {
                    int p = nf >> 1, j = (nf & 1) * 2;
                    mma_f32(acc[mf][nf], ah[mf], bhv[p][j], bhv[p][j+1]);
                }
            }
        }
    };

    // 3-stage pipeline, single barrier per chunk, compute-before-prefetch
    load_chunk(0, 0);
    load_chunk(1, 1);
    for (int c = 0; c < NCHUNK; c++) {
        if (c >= NCHUNK - 2) asm volatile("cp.async.wait_group 0;" ::: "memory");
        else                 asm volatile("cp.async.wait_group 1;" ::: "memory");
        __syncthreads();
        compute(c % STAGES);
        if (c + 2 < NCHUNK) load_chunk(c + 2, (c + 2) % STAGES);
    }

    // epilogue (+ optional fused GroupNorm stats, + optional fused outconv)
    __shared__ float ws[8][2][2];
    float* sv = (float*)smem_raw;                    // [128][128] staged tile (oc mode)
    if (ocw) __syncthreads();                        // mainloop smem reads done before overwrite
    #pragma unroll
    for (int mf = 0; mf < 2; mf++) {
        int rowA = o0 + m0 + mf * 16 + (lane >> 2);
        int rowB = rowA + 8;
        float bA = bias[rowA], bB = bias[rowB];
        float s = 0.f, q = 0.f;
        #pragma unroll
        for (int nf = 0; nf < 8; nf++) {
            int col = nw + nf * 8 + (lane & 3) * 2;
            float2 vA = make_float2(acc[mf][nf][0] + bA, acc[mf][nf][1] + bA);
            float2 vB = make_float2(acc[mf][nf][2] + bB, acc[mf][nf][3] + bB);
            if (stats) {
                s += vA.x + vA.y + vB.x + vB.y;
                q += vA.x*vA.x + vA.y*vA.y + vB.x*vB.x + vB.y*vB.y;
            }
            if (relu) {
                vA.x = fmaxf(vA.x, 0.f); vA.y = fmaxf(vA.y, 0.f);
                vB.x = fmaxf(vB.x, 0.f); vB.y = fmaxf(vB.y, 0.f);
            }
            if (out16) {
                __half* pA = out16 + ((size_t)nB * C_ + rowA) * T_ + t0;
                __half* pB = out16 + ((size_t)nB * C_ + rowB) * T_ + t0;
                *reinterpret_cast<__half2*>(pA + col) = __floats2half2_rn(vA.x, vA.y);
                *reinterpret_cast<__half2*>(pB + col) = __floats2half2_rn(vB.x, vB.y);
            } else {
                float* pA = out32 + ((size_t)nB * C_ + rowA) * T_ + t0;
                float* pB = out32 + ((size_t)nB * C_ + rowB) * T_ + t0;
                *reinterpret_cast<float2*>(pA + col) = vA;
                *reinterpret_cast<float2*>(pB + col) = vB;
            }
            if (ocw) {
                int rA = m0 + mf * 16 + (lane >> 2), rB = rA + 8;
                sv[rA * 128 + col] = vA.x; sv[rA * 128 + col + 1] = vA.y;
                sv[rB * 128 + col] = vB.x; sv[rB * 128 + col + 1] = vB.y;
            }
        }
        if (stats) {
            #pragma unroll
            for (int d = 16; d > 0; d >>= 1) {
                s += __shfl_xor_sync(0xffffffffu, s, d);
                q += __shfl_xor_sync(0xffffffffu, q, d);
            }
            if (lane == 0) { ws[wid][mf][0] = s; ws[wid][mf][1] = q; }
        }
    }
    if (stats) {
        __syncthreads();
        if (tid < 8) {
            int mw = tid >> 1, mf = tid & 1;
            float s = ws[mw*2+0][mf][0] + ws[mw*2+1][mf][0];
            float q = ws[mw*2+0][mf][1] + ws[mw*2+1][mf][1];
            int g = o0 / 16 + tid;
            g_psum[nB][g][blockIdx.x]   = s;
            g_psumsq[nB][g][blockIdx.x] = q;
        }
    }
    if (ocw) {
        float* swc  = (float*)(smem_raw + 65536);          // [2][128][3]
        float* sacc = (float*)(smem_raw + 65536 + 3072);   // [2][130]
        // load out_w slice for this o-block
        for (int i = tid; i < 768; i += 256) {
            int j2 = i / 384, r = (i % 384) / 3, k = i % 3;
            swc[i] = ocw[((size_t)j2 * C_ + o0 + r) * 3 + k];
        }
        for (int i = tid; i < 260; i += 256) sacc[i] = 0.f;
        __syncthreads();

        const int tl = tid & 127, j = tid >> 7;
        const float* wj = swc + j * 384;
        float p0 = 0.f, p1 = 0.f, p2 = 0.f;
        #pragma unroll 4
        for (int r = 0; r < 128; r++) {
            float v = sv[r * 128 + tl];
            p0 = fmaf(wj[r*3+0], v, p0);
            p1 = fmaf(wj[r*3+1], v, p1);
            p2 = fmaf(wj[r*3+2], v, p2);
        }
        __syncthreads();
        sacc[j * 130 + tl + 1] += p1;   // tap k=1 -> out t
        __syncthreads();
        sacc[j * 130 + tl + 2] += p0;   // tap k=0 -> out t+1
        __syncthreads();
        sacc[j * 130 + tl] += p2;       // tap k=2 -> out t-1
        __syncthreads();
        for (int i = tid; i < 260; i += 256) {
            int j2 = i / 130, slot = i % 130;
            g_ocp[nB][blockIdx.y][j2][blockIdx.x][slot] = sacc[i];
        }
    }
}

// ---------------- finalize GroupNorm stats (spread over 8 blocks) ----------------
__global__ void gn_finalize_kernel() {
    int idx = blockIdx.x * blockDim.x + threadIdx.x;
    if (idx >= N_ * G_) return;
    int n = idx / G_, g = idx % G_;
    float s = 0.f, q = 0.f;
    #pragma unroll
    for (int b = 0; b < NTB; b++) { s += g_psum[n][g][b]; q += g_psumsq[n][g][b]; }
    const float M = 16.f * T_;
    float m = s / M;
    float var = q / M - m * m;
    g_mean[idx] = m;
    g_rstd[idx] = rsqrtf(var + EPS_);
}

// ---------------- finalize fused outconv partials -> offset ----------------
__global__ __launch_bounds__(256) void oc_finalize_kernel(const float* __restrict__ ob,
                                                          float* __restrict__ out) {
    int idx = blockIdx.x * 256 + threadIdx.x;        // over N_*2*T_
    int t = idx & (T_ - 1);
    int j = (idx >> 12) & 1;
    int n = idx >> 13;
    float s = ob[j];
    int bx0 = t >> 7;
    #pragma unroll
    for (int by = 0; by < 4; by++) {
        #pragma unroll
        for (int d = -1; d <= 1; d++) {
            int bx = bx0 + d;
            if (bx < 0 || bx >= NTB) continue;
            int slot = t - bx * 128 + 1;
            if (slot < 0 || slot > 129) continue;
            s += g_ocp[n][by][j][bx][slot];
        }
    }
    out[((size_t)n * 2 + j) * T_ + t] = s;
}

// ---------------- normalize+relu -> hT fp16 (transposed), reads g_h16 ----------------
__global__ __launch_bounds__(256) void norm_t_kernel(const float* __restrict__ gamma,
                                                     const float* __restrict__ beta) {
    __shared__ float st[64][65];
    int n = blockIdx.z, c0 = blockIdx.y * 64, t0 = blockIdx.x * 64;
    for (int i = threadIdx.x; i < 64 * 64; i += 256) {
        int ci = i >> 6, t = i & 63;
        int c = c0 + ci;
        float v = __half2float(g_h16[((size_t)n * C_ + c) * T_ + t0 + t]);
        int gi = n * G_ + (c >> 4);
        v = fmaxf((v - g_mean[gi]) * g_rstd[gi] * gamma[c] + beta[c], 0.f);
        st[ci][t] = v;
    }
    __syncthreads();
    for (int i = threadIdx.x; i < 64 * 64; i += 256) {
        int ci = i & 63, t = i >> 6;
        size_t dst = ((size_t)n * TPAD + 1 + t0 + t) * C_ + c0 + ci;
        g_hT[dst] = __float2half_rn(st[ci][t]);
    }
}

// ---------------- bilinear sampling -> S0/S2 fp16 (reads hT, vectorized) ----------------
__global__ __launch_bounds__(256) void sample_kernel(const float* __restrict__ locs,
                                                     const int* __restrict__ stride_p) {
    const int n = blockIdx.y;
    int sv = *stride_p;
    float fs = (sv > 0 && sv < 1000000) ? (float)sv : __int_as_float(sv);

    const int ci2 = threadIdx.x;   // half2 index: channels 2*ci2, 2*ci2+1

    #pragma unroll
    for (int tt = 0; tt < 4; tt++) {
        int t = blockIdx.x * 4 + tt;
        float y1 = locs[((size_t)n * 2 + 0) * T_ + t] / fs;
        float y2 = locs[((size_t)n * 2 + 1) * T_ + t] / fs;

        float pos0 = (float)t - 1.0f - y1;
        float f0 = floorf(pos0);
        float wb0 = pos0 - f0;
        int i00 = (int)f0, i01 = i00 + 1;
        float m00 = (i00 >= 0 && i00 < T_) ? 1.f : 0.f;
        float m01 = (i01 >= 0 && i01 < T_) ? 1.f : 0.f;
        size_t r00 = ((size_t)n * TPAD + 1 + min(max(i00, 0), T_ - 1)) * C_;
        size_t r01 = ((size_t)n * TPAD + 1 + min(max(i01, 0), T_ - 1)) * C_;

        float pos2 = (float)t + 1.0f + y2;
        float f2 = floorf(pos2);
        float wb2 = pos2 - f2;
        int i20 = (int)f2, i21 = i20 + 1;
        float m20 = (i20 >= 0 && i20 < T_) ? 1.f : 0.f;
        float m21 = (i21 >= 0 && i21 < T_) ? 1.f : 0.f;
        size_t r20 = ((size_t)n * TPAD + 1 + min(max(i20, 0), T_ - 1)) * C_;
        size_t r21 = ((size_t)n * TPAD + 1 + min(max(i21, 0), T_ - 1)) * C_;

        size_t dst = ((size_t)n * TPAD + 1 + t) * C_;

        __half2 a0 = ((const __half2*)(g_hT + r00))[ci2];
        __half2 b0 = ((const __half2*)(g_hT + r01))[ci2];
        __half2 a2 = ((const __half2*)(g_hT + r20))[ci2];
        __half2 b2 = ((const __half2*)(g_hT + r21))[ci2];

        float w0a = (1.f - wb0) * m00, w0b = wb0 * m01;
        float w2a = (1.f - wb2) * m20, w2b = wb2 * m21;

        float s0x = __half2float(a0.x) * w0a + __half2float(b0.x) * w0b;
        float s0y = __half2float(a0.y) * w0a + __half2float(b0.y) * w0b;
        float s2x = __half2float(a2.x) * w2a + __half2float(b2.x) * w2b;
        float s2y = __half2float(a2.y) * w2a + __half2float(b2.y) * w2b;

        ((__half2*)(g_S0 + dst))[ci2] = __floats2half2_rn(s0x, s0y);
        ((__half2*)(g_S2 + dst))[ci2] = __floats2half2_rn(s2x, s2y);
    }
}

// ---------------------------------------------------------------------------
extern "C" void kernel_launch(void* const* d_in, const int* in_sizes, int n_in,
                              void* d_out, int out_size) {
    const float* feat   = (const float*)d_in[0];
    const float* locs   = (const float*)d_in[1];
    const float* conv_w = (const float*)d_in[2];
    const float* conv_b = (const float*)d_in[3];
    const float* gn_g   = (const float*)d_in[4];
    const float* gn_b   = (const float*)d_in[5];
    const float* dcn_w  = (const float*)d_in[6];
    const float* dcn_b  = (const float*)d_in[7];
    const float* out_w  = (const float*)d_in[8];
    const float* out_b  = (const float*)d_in[9];
    const int*   stride = (const int*)d_in[10];

    float* out      = (float*)d_out;
    float* out_feat = (float*)d_out + OFFSET_ELEMS;

    __half *w1, *w2, *xt, *ht, *s0, *s2, *hbuf16;
    cudaGetSymbolAddress((void**)&w1, g_W);  w2 = w1 + 3*C_*C_;
    cudaGetSymbolAddress((void**)&xt, g_xT);
    cudaGetSymbolAddress((void**)&ht, g_hT);
    cudaGetSymbolAddress((void**)&s0, g_S0);
    cudaGetSymbolAddress((void**)&s2, g_S2);
    cudaGetSymbolAddress((void**)&hbuf16, g_h16);

    const int SMEM_BYTES = STAGES * STAGE_BYTES;   // 96 KB
    cudaFuncSetAttribute(gemm_kernel, cudaFuncAttributeMaxDynamicSharedMemorySize, SMEM_BYTES);

    dim3 tr_grid(T_/64, C_/64, N_);
    dim3 gemm_grid(T_/TNT, C_/TMT, N_);   // (32, 4, 8) = 1024

    prep_w_kernel<<<dim3(512, 2), 256>>>(conv_w, dcn_w);
    prep_x_kernel<<<tr_grid, 256>>>(feat);
    zero_guard_kernel<<<(N_*C_ + 255)/256, 256>>>();
    gemm_kernel<<<gemm_grid, 256, SMEM_BYTES>>>(w1,
        xt, xt, xt, -1, 0, 1, conv_b, nullptr, hbuf16, nullptr, 0, 1);
    gn_finalize_kernel<<<8, 32>>>();
    norm_t_kernel<<<tr_grid, 256>>>(gn_g, gn_b);
    sample_kernel<<<dim3(T_/4, N_), 256>>>(locs, stride);
    gemm_kernel<<<gemm_grid, 256, SMEM_BYTES>>>(w2,
        s0, ht, s2, 0, 0, 0, dcn_b, out_feat, nullptr, out_w, 1, 0);
    oc_finalize_kernel<<<(N_*2*T_)/256, 256>>>(out_b, out);
}